// round 11
// baseline (speedup 1.0000x reference)
#include <cuda_runtime.h>

#define NQ     14
#define DEPTH  6
#define DIM    16384
#define NGATES (NQ * DEPTH)
#define NTHR   512

typedef unsigned long long u64;

// Bank-conflict-free swizzle: permute low 5 address bits by bits 5..9.
// In every pass layout below, low5(addr) = lane ^ const -> conflict-free LDS.64/STS.64.
__device__ __forceinline__ int swz(int i) { return i ^ ((i >> 5) & 31); }

__device__ __forceinline__ u64 pk(float x, float y) {
    u64 r; asm("mov.b64 %0, {%1, %2};" : "=l"(r) : "f"(x), "f"(y)); return r;
}
__device__ __forceinline__ void upk(u64 v, float& x, float& y) {
    asm("mov.b64 {%0, %1}, %2;" : "=f"(x), "=f"(y) : "l"(v));
}

// RY butterfly on one complex pair, packed f32x2 (re,im rotated simultaneously):
//   a' = ct*a - st*c ;  c' = st*a + ct*c      4 packed ops instead of 8 scalar.
__device__ __forceinline__ void rot(u64& a, u64& c, u64 ct2, u64 st2, u64 nst2) {
    u64 t0, t1, na, nc;
    asm("mul.rn.f32x2 %0, %1, %2;"     : "=l"(t0) : "l"(nst2), "l"(c));
    asm("mul.rn.f32x2 %0, %1, %2;"     : "=l"(t1) : "l"(st2),  "l"(a));
    asm("fma.rn.f32x2 %0, %1, %2, %3;" : "=l"(na) : "l"(ct2), "l"(a), "l"(t0));
    asm("fma.rn.f32x2 %0, %1, %2, %3;" : "=l"(nc) : "l"(ct2), "l"(c), "l"(t1));
    a = na; c = nc;
}

// Index maps: full statevector index as a function of (thread t, register slot j).
// A: j = index bits 0..4   (gate positions 0..4  -> qubits 13..9)
// B: j3..j0 = bits 5..8, j4 = bit 9              (positions 5..8 -> qubits 8..5)
// C: j = index bits 9..13  (positions 9..13 -> qubits 4..0)
__device__ __forceinline__ int idxA(int t, int j) { return (t << 5) | j; }
__device__ __forceinline__ int idxB(int t, int j) {
    return (t & 31) | ((j & 15) << 5) | ((j >> 4) << 9) | ((t >> 5) << 10);
}
__device__ __forceinline__ int idxC(int t, int j) { return t | (j << 9); }

#define APPLY_SET(NB, QOF)                                              \
    _Pragma("unroll")                                                   \
    for (int bb = 0; bb < (NB); bb++) {                                 \
        const int g = gbase + ((QOF) - bb);                             \
        const u64 ct2 = g_ct2[g], st2 = g_st2[g], nst2 = g_nst2[g];     \
        _Pragma("unroll")                                               \
        for (int j = 0; j < 32; j++) {                                  \
            if (j & (1 << bb)) continue;                                \
            rot(v[j], v[j | (1 << bb)], ct2, st2, nst2);                \
        }                                                               \
    }

// set A: 5 bits, qubit = 13-bb ; set B: 4 bits, qubit = 8-bb ; set C: 5 bits, qubit = 4-bb
#define APPLY_A() APPLY_SET(5, NQ - 1)
#define APPLY_B() APPLY_SET(4, 8)
#define APPLY_C() APPLY_SET(5, 4)

// CZ chain diagonal: sign = (-1)^popc(i & (i>>1)), branchless sign-bit XOR.
#define APPLY_CZ(IDX)                                                   \
    _Pragma("unroll")                                                   \
    for (int j = 0; j < 32; j++) {                                      \
        int i = IDX(t, j);                                              \
        u64 par = (u64)(__popc(i & (i >> 1)) & 1);                      \
        v[j] ^= (par << 63) | (par << 31);                              \
    }

#define LOAD_V(IDX)  _Pragma("unroll") for (int j = 0; j < 32; j++) v[j] = state[swz(IDX(t, j))];
#define STORE_V(IDX) _Pragma("unroll") for (int j = 0; j < 32; j++) state[swz(IDX(t, j))] = v[j];

__global__ void __launch_bounds__(NTHR, 1)
qsim_kernel(const float* __restrict__ x,      // (512, 14)
            const float* __restrict__ theta,  // (84,)
            const float* __restrict__ hw,     // (2, 14)
            const float* __restrict__ hb,     // (2,)
            float* __restrict__ out)          // (512, 2)
{
    extern __shared__ u64 state[];              // DIM packed complex amplitudes (swizzled)
    __shared__ u64 g_ct2[NGATES], g_st2[NGATES], g_nst2[NGATES];
    __shared__ float s_c[NQ], s_s[NQ];
    __shared__ float zacc[NQ];                  // z_p = sum pr*(1-2*bit_p)

    const int b = blockIdx.x;
    const int t = threadIdx.x;

    if (t < NGATES) {
        float h = 0.5f * theta[t];
        float ct = cosf(h), st = sinf(h);
        g_ct2[t] = pk(ct, ct); g_st2[t] = pk(st, st); g_nst2[t] = pk(-st, -st);
    }
    if (t < NQ) { float h = 0.5f * x[b * NQ + t]; s_c[t] = cosf(h); s_s[t] = sinf(h); zacc[t] = 0.0f; }
    __syncthreads();

    u64 v[32];

    // ===== pass 1: initial product state built directly in layout A, then A(layer 0) =====
    // amp(i) = prod_q (bit_q ? sin(x_q/2) : cos(x_q/2)) * (-i)^popc(i); qubit q at bit NQ-1-q.
    // Layout A: i = (t<<5)|j -> bits 5..13 are thread-uniform: factor them out once.
    {
        float tb = 1.0f;
        #pragma unroll
        for (int p = 5; p < NQ; p++)
            tb *= ((t >> (p - 5)) & 1) ? s_s[NQ - 1 - p] : s_c[NQ - 1 - p];
        const int pt = __popc(t);
        #pragma unroll
        for (int j = 0; j < 32; j++) {
            float mag = tb;
            #pragma unroll
            for (int p = 0; p < 5; p++)
                mag *= ((j >> p) & 1) ? s_s[NQ - 1 - p] : s_c[NQ - 1 - p];
            int k = (pt + __popc(j)) & 3;   // (-i)^k: re=[1,0,-1,0], im=[0,-1,0,1]
            float re = (k == 0) ? mag : ((k == 2) ? -mag : 0.0f);
            float im = (k == 1) ? -mag : ((k == 3) ? mag : 0.0f);
            v[j] = pk(re, im);
        }
    }
    {
        const int gbase = 0;
        APPLY_A();
    }
    STORE_V(idxA);
    __syncthreads();

    // ===== layer pairs: B(d) | C(d)+CZ+C(d+1) | B(d+1) | A(d+1)+CZ[+A(d+2)] =====
    // NOT unrolled: keeps the hot SASS body at one copy so it stays inside the I$
    // L1.5/transition region instead of ~80 KB at trip-count-3 full unroll.
    #pragma unroll 1
    for (int dp = 0; dp < DEPTH; dp += 2) {
        const int gb0 = dp * NQ;
        const int gb1 = gb0 + NQ;

        // ---- B(dp) ----
        LOAD_V(idxB);
        { const int gbase = gb0; APPLY_B(); }
        STORE_V(idxB);
        __syncthreads();

        // ---- C(dp) + CZ(dp) + C(dp+1) ----
        LOAD_V(idxC);
        { const int gbase = gb0; APPLY_C(); }
        APPLY_CZ(idxC);
        { const int gbase = gb1; APPLY_C(); }
        STORE_V(idxC);
        __syncthreads();

        // ---- B(dp+1) ----
        LOAD_V(idxB);
        { const int gbase = gb1; APPLY_B(); }
        STORE_V(idxB);
        __syncthreads();

        // ---- A(dp+1) + CZ(dp+1) [+ A(dp+2)] ----
        LOAD_V(idxA);
        { const int gbase = gb1; APPLY_A(); }
        APPLY_CZ(idxA);
        if (dp + 2 < DEPTH) {
            const int gbase = gb1 + NQ;
            APPLY_A();
            STORE_V(idxA);
            __syncthreads();
        }
        // last iteration: v[] holds the final state in layout A; no store needed.
    }

    // ---- probabilities -> signed per-bit sums z_p = sum pr*(1-2*bit_p), from registers ----
    // Final layout A: i = (t<<5)|j.
    //   bits 0..4  <- j      : per-slot signed sums (zs[0..4])
    //   bits 5..9  <- t&31   : lane-dependent sign * tot (zs[5..9], built pre-reduction)
    //   bits 10..13<- t>>5   : WARP-UNIFORM sign -> no shuffle channel needed;
    //                          leader reconstructs from reduced tot.
    float zs[10];
    #pragma unroll
    for (int p = 0; p < 10; p++) zs[p] = 0.0f;
    float tot = 0.0f;
    #pragma unroll
    for (int j = 0; j < 32; j++) {
        float re, im; upk(v[j], re, im);
        float pr = fmaf(re, re, im * im);
        tot += pr;
        #pragma unroll
        for (int p = 0; p < 5; p++)
            zs[p] += ((j >> p) & 1) ? -pr : pr;
    }
    #pragma unroll
    for (int p = 5; p < 10; p++)
        zs[p] = ((t >> (p - 5)) & 1) ? -tot : tot;

    #pragma unroll
    for (int o = 16; o; o >>= 1) {
        tot += __shfl_xor_sync(0xffffffffu, tot, o);
        #pragma unroll
        for (int p = 0; p < 10; p++)
            zs[p] += __shfl_xor_sync(0xffffffffu, zs[p], o);
    }
    if ((t & 31) == 0) {
        #pragma unroll
        for (int p = 0; p < 10; p++) atomicAdd(&zacc[p], zs[p]);
        #pragma unroll
        for (int p = 10; p < NQ; p++) {
            float zu = ((t >> (p - 5)) & 1) ? -tot : tot;   // t>>5 bits: warp-uniform
            atomicAdd(&zacc[p], zu);
        }
    }
    __syncthreads();

    // ---- head: out column p corresponds to bit position p (reference reverses qubit order) ----
    if (t < 2) {
        float lg = hb[t];
        #pragma unroll
        for (int p = 0; p < NQ; p++)
            lg = fmaf(zacc[p], hw[t * NQ + p], lg);
        out[b * 2 + t] = lg;
    }
}

extern "C" void kernel_launch(void* const* d_in, const int* in_sizes, int n_in,
                              void* d_out, int out_size)
{
    const float* x     = (const float*)d_in[0];
    const float* theta = (const float*)d_in[1];
    const float* hw    = (const float*)d_in[2];
    const float* hb    = (const float*)d_in[3];
    float* out = (float*)d_out;

    const int B = in_sizes[0] / NQ;            // 512
    const size_t smem = DIM * sizeof(u64);     // 128 KB dynamic

    cudaFuncSetAttribute(qsim_kernel, cudaFuncAttributeMaxDynamicSharedMemorySize, (int)smem);
    qsim_kernel<<<B, NTHR, smem>>>(x, theta, hw, hb, out);
}